// round 7
// baseline (speedup 1.0000x reference)
#include <cuda_runtime.h>
#include <cstdint>

#define NN 16
#define KK 4
#define BB 16384
#define DD 64
#define FINAL_ID 15
#define LMAX 96   // max (padded) sparse indices per row; Binomial(256,0.1) >8 sigma safe

// packed spike masks: one 64-bit mask per (node,row): bit d = (s_prev[n,b,d] != 0)
__device__ uint2 g_packed[NN * BB];
// per-(target node, row) index lists into the 320-row W tile (u16, padded w/ 320)
__device__ uint16_t g_idx[(size_t)NN * BB * LMAX];
// per row-PAIR padded count (multiple of 8, same for both rows of the pair)
__device__ int g_cnt[NN * BB / 2];

// ---------------------------------------------------------------------------
// Kernel 0: pack s_prev (binary 0/1 floats) into bitmasks.
// ---------------------------------------------------------------------------
__global__ void pack_kernel(const float* __restrict__ s_prev) {
    const int ROWS_PER_WARP = 8;
    int warp = (blockIdx.x * blockDim.x + threadIdx.x) >> 5;
    int lane = threadIdx.x & 31;
    int row0 = warp * ROWS_PER_WARP;
    #pragma unroll
    for (int r = 0; r < ROWS_PER_WARP; r++) {
        int row = row0 + r;
        float v0 = s_prev[(size_t)row * DD + lane];
        float v1 = s_prev[(size_t)row * DD + 32 + lane];
        unsigned lo = __ballot_sync(0xffffffffu, v0 != 0.0f);
        unsigned hi = __ballot_sync(0xffffffffu, v1 != 0.0f);
        if (lane == 0) g_packed[row] = make_uint2(lo, hi);
    }
}

// ---------------------------------------------------------------------------
// Kernel 1: build index lists for a ROW PAIR per thread; both lists padded
// (with idx=320 -> zero W row) to the common 8-multiple max so the fused
// kernel's half-warp loop is divergence-free.
// ---------------------------------------------------------------------------
__global__ void build_lists_kernel(const int* __restrict__ conn) {
    int t = blockIdx.x * blockDim.x + threadIdx.x;   // 0 .. NN*BB/2-1
    int n  = t >> 13;                                // / (BB/2)
    int bp = t & (BB / 2 - 1);

    int src[KK];
    #pragma unroll
    for (int k = 0; k < KK; k++) src[k] = conn[n * KK + k];

    int cnts[2];
    #pragma unroll
    for (int h = 0; h < 2; h++) {
        int b = 2 * bp + h;
        uint16_t* dst = g_idx + ((size_t)n * BB + b) * LMAX;
        int cnt = 0;
        #pragma unroll
        for (int k = 0; k < KK; k++) {
            uint2 m = g_packed[src[k] * BB + b];
            #pragma unroll
            for (int w = 0; w < 2; w++) {
                unsigned mm = (w == 0) ? m.x : m.y;
                int base = k * 64 + w * 32;
                while (mm) {
                    int bit = __ffs(mm) - 1;
                    mm &= mm - 1;
                    dst[cnt++] = (uint16_t)(base + bit);
                }
            }
        }
        cnts[h] = cnt;
    }
    int m8 = ((cnts[0] > cnts[1] ? cnts[0] : cnts[1]) + 7) & ~7;
    #pragma unroll
    for (int h = 0; h < 2; h++) {
        uint16_t* dst = g_idx + ((size_t)n * BB + 2 * bp + h) * LMAX;
        for (int i = cnts[h]; i < m8; i++) dst[i] = 320;
    }
    g_cnt[t] = m8;
}

// ---- packed f32x2 helpers (bit-identical per lane to scalar IEEE ops) -----
__device__ __forceinline__ unsigned long long pack2(float x) {
    unsigned long long r;
    asm("mov.b64 %0, {%1, %1};" : "=l"(r) : "f"(x));
    return r;
}
__device__ __forceinline__ void addx2(unsigned long long& a, unsigned long long w) {
    asm("add.rn.f32x2 %0, %0, %1;" : "+l"(a) : "l"(w));
}
__device__ __forceinline__ void fmax2(unsigned long long& a, unsigned long long w,
                                      unsigned long long x) {
    asm("fma.rn.f32x2 %0, %1, %2, %0;" : "+l"(a) : "l"(w), "l"(x));
}

// ---------------------------------------------------------------------------
// Kernel 2: fused Dense + sparse-accumulate + LIF.
// 512-thread blocks, 2 blocks/SM (32 warps). Each HALF-WARP owns one batch
// row; thread owns 4 output cols {4*ln..4*ln+3} (ln = lane&15). A warp
// processes 2 rows per issue slot. 2 groups x 4 row-pairs = 16 rows/warp.
// ---------------------------------------------------------------------------
__global__ __launch_bounds__(512, 2)
void snn_fused_kernel(const float* __restrict__ inputs,
                      const float* __restrict__ u,
                      const float* __restrict__ i_syn,
                      const float* __restrict__ W,
                      const float* __restrict__ bias,
                      float* __restrict__ out) {
    extern __shared__ float Wsh[];                 // [321][64]; row 320 = zeros

    const int n    = blockIdx.x;
    const int tile = blockIdx.y;
    const int tid  = threadIdx.x;
    const int lane = tid & 31;
    const int warp = tid >> 5;
    const int ln   = lane & 15;                    // col-group within half-warp
    const int half = lane >> 4;                    // which row of the pair

    // cooperative load of W[n] (320x64 floats) into smem, float4 vectorized
    {
        const float4* Wg  = (const float4*)(W + (size_t)n * 320 * 64);
        float4*       Ws4 = (float4*)Wsh;
        #pragma unroll
        for (int i = 0; i < 10; i++)
            Ws4[tid + i * 512] = Wg[tid + i * 512];
        if (tid < 16)                               // zero pad row 320
            ((float4*)(Wsh + 320 * 64))[tid] = make_float4(0.f, 0.f, 0.f, 0.f);
    }

    const float4 bv = *(const float4*)(bias + n * DD + 4 * ln);
    const unsigned long long bvA = ((const unsigned long long*)&bv)[0];
    const unsigned long long bvB = ((const unsigned long long*)&bv)[1];
    __syncthreads();

    float* s_out = out + (size_t)BB * DD;
    float* u_out = s_out + (size_t)NN * BB * DD;
    float* i_out = u_out + (size_t)NN * BB * DD;

    const int rowbase = tile * 256 + warp * 16;

    for (int g = 0; g < 2; g++) {
        const int p0 = rowbase + g * 8;            // 4 row-pairs: rows p0..p0+7

        unsigned long long accA[4], accB[4];       // cols {4ln,4ln+1} / {4ln+2,4ln+3}
        #pragma unroll
        for (int rp = 0; rp < 4; rp++) { accA[rp] = bvA; accB[rp] = bvB; }

        // ---- dense block: inputs(64) @ W[256:320, :], 8 rows (4 pairs) ----
        #pragma unroll
        for (int dd = 0; dd < 16; dd++) {
            float4 xv[4];
            #pragma unroll
            for (int rp = 0; rp < 4; rp++)
                xv[rp] = __ldg((const float4*)(inputs + (p0 + 2 * rp + half) * DD + dd * 4));
            #pragma unroll
            for (int j = 0; j < 4; j++) {
                ulonglong2 w = *(const ulonglong2*)(Wsh + (256 + dd * 4 + j) * 64 + 4 * ln);
                #pragma unroll
                for (int rp = 0; rp < 4; rp++) {
                    float x = (j == 0) ? xv[rp].x :
                              (j == 1) ? xv[rp].y :
                              (j == 2) ? xv[rp].z : xv[rp].w;
                    unsigned long long xx = pack2(x);
                    fmax2(accA[rp], w.x, xx);
                    fmax2(accB[rp], w.y, xx);
                }
            }
        }

        // ---- sparse block (indexed, half-warp per row) + LIF per pair ----
        #pragma unroll
        for (int rp = 0; rp < 4; rp++) {
            const int b   = p0 + 2 * rp + half;
            const int row = n * BB + b;
            const size_t base = ((size_t)row) * DD + 4 * ln;
            float4 uu = *(const float4*)(u + base);
            float4 is = *(const float4*)(i_syn + base);

            const uint16_t* lp = g_idx + (size_t)row * LMAX;
            const int cnt = g_cnt[(n * BB + p0 + 2 * rp) >> 1];   // uniform per warp

            unsigned long long aA = accA[rp], aB = accB[rp];
            unsigned long long aA2 = 0, aB2 = 0;
            for (int i = 0; i < cnt; i += 4) {
                ushort4 q = *(const ushort4*)(lp + i);
                ulonglong2 w0 = *(const ulonglong2*)(Wsh + q.x * 64 + 4 * ln);
                ulonglong2 w1 = *(const ulonglong2*)(Wsh + q.y * 64 + 4 * ln);
                ulonglong2 w2 = *(const ulonglong2*)(Wsh + q.z * 64 + 4 * ln);
                ulonglong2 w3 = *(const ulonglong2*)(Wsh + q.w * 64 + 4 * ln);
                addx2(aA,  w0.x);  addx2(aB,  w0.y);
                addx2(aA2, w1.x);  addx2(aB2, w1.y);
                addx2(aA,  w2.x);  addx2(aB,  w2.y);
                addx2(aA2, w3.x);  addx2(aB2, w3.y);
            }
            addx2(aA, aA2);
            addx2(aB, aB2);

            float a[4];
            *(unsigned long long*)&a[0] = aA;
            *(unsigned long long*)&a[2] = aB;
            const float uv[4] = {uu.x, uu.y, uu.z, uu.w};
            const float iv[4] = {is.x, is.y, is.z, is.w};
            float4 sv4, uo4, in4;
            float* svp = (float*)&sv4;
            float* uop = (float*)&uo4;
            float* inp = (float*)&in4;
            #pragma unroll
            for (int c = 0; c < 4; c++) {
                float inew = fmaf(0.9f, iv[c], a[c]);
                float unew = fmaf(0.95f, uv[c], 0.05f * inew);
                float sv   = (unew - 1.0f > 0.0f) ? 1.0f : 0.0f;
                float uo   = (sv > 0.5f) ? 0.0f : unew;
                svp[c] = sv; uop[c] = uo; inp[c] = inew;
            }

            *(float4*)(s_out + base) = sv4;
            *(float4*)(u_out + base) = uo4;
            *(float4*)(i_out + base) = in4;
            if (n == FINAL_ID)
                *(float4*)(out + (size_t)b * DD + 4 * ln) = sv4;
        }
    }
}

// ---------------------------------------------------------------------------
extern "C" void kernel_launch(void* const* d_in, const int* in_sizes, int n_in,
                              void* d_out, int out_size) {
    const float* inputs = (const float*)d_in[0];
    const float* u      = (const float*)d_in[1];
    const float* i_syn  = (const float*)d_in[2];
    const float* s_prev = (const float*)d_in[3];
    const float* W      = (const float*)d_in[4];
    const float* bias   = (const float*)d_in[5];
    const int*   conn   = (const int*)d_in[6];
    float* out = (float*)d_out;

    pack_kernel<<<(NN * BB) / 64, 256>>>(s_prev);
    build_lists_kernel<<<(NN * BB / 2) / 256, 256>>>(conn);

    const int smem = 321 * 64 * sizeof(float);     // ~80.3 KB (incl. zero row)
    cudaFuncSetAttribute(snn_fused_kernel,
                         cudaFuncAttributeMaxDynamicSharedMemorySize, smem);

    dim3 grid(NN, BB / 256);
    snn_fused_kernel<<<grid, 512, smem>>>(inputs, u, i_syn, W, bias, out);
}

// round 9
// speedup vs baseline: 1.5947x; 1.5947x over previous
#include <cuda_runtime.h>
#include <cuda_bf16.h>
#include <cstdint>

#define NN 16
#define KK 4
#define BB 16384
#define DD 64
#define FINAL_ID 15
#define BSTRIDE 712      // 704 + 8 pad (bf16 elems per B-image row)

// ---------------- scratch (__device__ globals; no allocs) -------------------
__device__ uint2    g_packed[NN * BB];              // spike bitmasks
__device__ unsigned g_xhi[BB * 32];                 // bf16x2 pairs of hi(inputs)
__device__ unsigned g_xlo[BB * 32];                 // bf16x2 pairs of lo(inputs)
__device__ unsigned short g_Bimg[NN * 64 * BSTRIDE];// B image [n][c][k]

// ---------------------------------------------------------------------------
// Kernel 0: pack s_prev (binary 0/1 floats) into bitmasks.
// ---------------------------------------------------------------------------
__global__ void pack_kernel(const float* __restrict__ s_prev) {
    const int ROWS_PER_WARP = 8;
    int warp = (blockIdx.x * blockDim.x + threadIdx.x) >> 5;
    int lane = threadIdx.x & 31;
    int row0 = warp * ROWS_PER_WARP;
    #pragma unroll
    for (int r = 0; r < ROWS_PER_WARP; r++) {
        int row = row0 + r;
        float v0 = s_prev[(size_t)row * DD + lane];
        float v1 = s_prev[(size_t)row * DD + 32 + lane];
        unsigned lo = __ballot_sync(0xffffffffu, v0 != 0.0f);
        unsigned hi = __ballot_sync(0xffffffffu, v1 != 0.0f);
        if (lane == 0) g_packed[row] = make_uint2(lo, hi);
    }
}

// ---------------------------------------------------------------------------
// Kernel 1: split inputs into bf16 hi/lo pairs (packed bf16x2, even col low).
// ---------------------------------------------------------------------------
__global__ void prep_x_kernel(const float* __restrict__ inputs) {
    int idx = blockIdx.x * blockDim.x + threadIdx.x;   // 0 .. BB*32-1
    float x0 = inputs[idx * 2], x1 = inputs[idx * 2 + 1];
    __nv_bfloat16 h0 = __float2bfloat16(x0), h1 = __float2bfloat16(x1);
    float r0 = x0 - __bfloat162float(h0);
    float r1 = x1 - __bfloat162float(h1);
    __nv_bfloat16 l0 = __float2bfloat16(r0), l1 = __float2bfloat16(r1);
    unsigned short b0 = *(unsigned short*)&h0, b1 = *(unsigned short*)&h1;
    unsigned short c0 = *(unsigned short*)&l0, c1 = *(unsigned short*)&l1;
    g_xhi[idx] = ((unsigned)b1 << 16) | b0;
    g_xlo[idx] = ((unsigned)c1 << 16) | c0;
}

// ---------------------------------------------------------------------------
// Kernel 2: build B image [n][c][k], k-major rows per output col c.
// k 0..255   : hi(Ws[k][c])        (spike cols, hi)
// k 256..319 : hi(Wd[k][c])        (pairs x_hi)
// k 320..383 : hi(Wd[k-64][c])     (Wd_hi again, pairs x_lo)
// k 384..639 : lo(Ws[k-384][c])    (spike cols, lo)
// k 640..703 : lo(Wd[k-384][c])    (pairs x_hi)
// ---------------------------------------------------------------------------
__global__ void prep_w_kernel(const float* __restrict__ W) {
    int n = blockIdx.x >> 6, c = blockIdx.x & 63;
    const float* Wn = W + (size_t)n * 320 * 64;
    for (int k = threadIdx.x; k < 704; k += 256) {
        unsigned short bits;
        if (k < 384) {
            int i = (k < 320) ? k : k - 64;
            __nv_bfloat16 h = __float2bfloat16(Wn[i * 64 + c]);
            bits = *(unsigned short*)&h;
        } else {
            int j = k - 384;                   // 0..319
            float v = Wn[j * 64 + c];
            __nv_bfloat16 h = __float2bfloat16(v);
            float r = v - __bfloat162float(h);
            __nv_bfloat16 l = __float2bfloat16(r);
            bits = *(unsigned short*)&l;
        }
        g_Bimg[(size_t)(n * 64 + c) * BSTRIDE + k] = bits;
    }
}

// ---------------- warp MMA helpers -----------------------------------------
__device__ __forceinline__ uint32_t smem_u32(const void* p) {
    uint32_t a;
    asm("{ .reg .u64 t; cvta.to.shared.u64 t, %1; cvt.u32.u64 %0, t; }"
        : "=r"(a) : "l"(p));
    return a;
}
__device__ __forceinline__ void mma16816(float* c, uint32_t a0, uint32_t a1,
                                         uint32_t a2, uint32_t a3,
                                         uint32_t b0, uint32_t b1) {
    asm volatile(
        "mma.sync.aligned.m16n8k16.row.col.f32.bf16.bf16.f32 "
        "{%0,%1,%2,%3}, {%4,%5,%6,%7}, {%8,%9}, {%0,%1,%2,%3};"
        : "+f"(c[0]), "+f"(c[1]), "+f"(c[2]), "+f"(c[3])
        : "r"(a0), "r"(a1), "r"(a2), "r"(a3), "r"(b0), "r"(b1));
}
__device__ __forceinline__ void ldm4(uint32_t& b0, uint32_t& b1,
                                     uint32_t& b2, uint32_t& b3, uint32_t addr) {
    asm volatile("ldmatrix.sync.aligned.m8n8.x4.shared.b16 {%0,%1,%2,%3}, [%4];"
                 : "=r"(b0), "=r"(b1), "=r"(b2), "=r"(b3) : "r"(addr));
}
// 2-bit spike pair -> packed bf16x2 {bit0 -> 1.0 low, bit1 -> 1.0 high}
__device__ __forceinline__ uint32_t p2b(unsigned p) {
    return (p & 1u) * 0x3F80u + (p >> 1) * 0x3F800000u;
}

// ---------------------------------------------------------------------------
// Kernel 3: per (node, 128-row tile) split-bf16 HMMA GEMM + LIF epilogue.
// 256 threads = 8 warps; warp owns 16 batch rows. B tile (64x704 bf16,
// stride 712) in smem; A fragments built in registers from masks / g_x*.
// ---------------------------------------------------------------------------
__global__ __launch_bounds__(256, 2)
void snn_mma_kernel(const float* __restrict__ u,
                    const float* __restrict__ i_syn,
                    const float* __restrict__ bias,
                    const int*   __restrict__ conn,
                    float* __restrict__ out) {
    extern __shared__ unsigned short Bs[];          // [64][BSTRIDE]
    const int tid = threadIdx.x;
    const int w = tid >> 5, lane = tid & 31;
    const int n = blockIdx.x, tile = blockIdx.y;

    // copy pre-built B image into smem (89 KB, uint4)
    {
        const uint4* src = (const uint4*)(g_Bimg + (size_t)n * 64 * BSTRIDE);
        uint4* dst = (uint4*)Bs;
        for (int i = tid; i < 64 * BSTRIDE / 8; i += 256) dst[i] = src[i];
    }
    __syncthreads();

    const int gr = lane >> 2, tg = lane & 3;
    const int rbase = tile * 128 + w * 16;
    const int row0 = rbase + gr, row1 = row0 + 8;

    uint2 ml[4], mh[4];
    #pragma unroll
    for (int k = 0; k < 4; k++) {
        int s = __ldg(conn + n * KK + k);
        ml[k] = g_packed[s * BB + row0];
        mh[k] = g_packed[s * BB + row1];
    }

    float acc[8][4];
    #pragma unroll
    for (int nt = 0; nt < 8; nt++)
        #pragma unroll
        for (int q = 0; q < 4; q++) acc[nt][q] = 0.0f;

    const uint32_t sbase = smem_u32(Bs);
    const int lrow = (lane & 7) + ((lane >> 4) & 1) * 8; // row in 16-row npair
    const int lkof = ((lane >> 3) & 1) * 8;              // k offset 0/8

    // ---- pass 1: K cols 0..383 (spike-hi, x_hi*Wd_hi, x_lo*Wd_hi) ----
    #pragma unroll
    for (int kc = 0; kc < 24; kc++) {
        uint32_t a0, a1, a2, a3;
        if (kc < 16) {
            const int s = kc >> 2, q = kc & 3;
            unsigned fl = ((q & 2) ? ml[s].y : ml[s].x) >> ((q & 1) * 16);
            unsigned fh = ((q & 2) ? mh[s].y : mh[s].x) >> ((q & 1) * 16);
            a0 = p2b((fl >> (2 * tg)) & 3);
            a1 = p2b((fh >> (2 * tg)) & 3);
            a2 = p2b((fl >> (2 * tg + 8)) & 3);
            a3 = p2b((fh >> (2 * tg + 8)) & 3);
        } else if (kc < 20) {
            const int j = kc - 16;
            a0 = __ldg(g_xhi + row0 * 32 + j * 8 + tg);
            a2 = __ldg(g_xhi + row0 * 32 + j * 8 + tg + 4);
            a1 = __ldg(g_xhi + row1 * 32 + j * 8 + tg);
            a3 = __ldg(g_xhi + row1 * 32 + j * 8 + tg + 4);
        } else {
            const int j = kc - 20;
            a0 = __ldg(g_xlo + row0 * 32 + j * 8 + tg);
            a2 = __ldg(g_xlo + row0 * 32 + j * 8 + tg + 4);
            a1 = __ldg(g_xlo + row1 * 32 + j * 8 + tg);
            a3 = __ldg(g_xlo + row1 * 32 + j * 8 + tg + 4);
        }
        const int k0 = kc * 16;
        #pragma unroll
        for (int np = 0; np < 4; np++) {
            uint32_t b0, b1, b2, b3;
            uint32_t addr = sbase + ((np * 16 + lrow) * BSTRIDE + k0 + lkof) * 2;
            ldm4(b0, b1, b2, b3, addr);
            mma16816(acc[2 * np],     a0, a1, a2, a3, b0, b1);
            mma16816(acc[2 * np + 1], a0, a1, a2, a3, b2, b3);
        }
    }

    // ---- pass 2: K cols 384..703 (spike-lo, x_hi*Wd_lo) ----
    #pragma unroll
    for (int kc = 0; kc < 20; kc++) {
        uint32_t a0, a1, a2, a3;
        if (kc < 16) {
            const int s = kc >> 2, q = kc & 3;
            unsigned fl = ((q & 2) ? ml[s].y : ml[s].x) >> ((q & 1) * 16);
            unsigned fh = ((q & 2) ? mh[s].y : mh[s].x) >> ((q & 1) * 16);
            a0 = p2b((fl >> (2 * tg)) & 3);
            a1 = p2b((fh >> (2 * tg)) & 3);
            a2 = p2b((fl >> (2 * tg + 8)) & 3);
            a3 = p2b((fh >> (2 * tg + 8)) & 3);
        } else {
            const int j = kc - 16;
            a0 = __ldg(g_xhi + row0 * 32 + j * 8 + tg);
            a2 = __ldg(g_xhi + row0 * 32 + j * 8 + tg + 4);
            a1 = __ldg(g_xhi + row1 * 32 + j * 8 + tg);
            a3 = __ldg(g_xhi + row1 * 32 + j * 8 + tg + 4);
        }
        const int k0 = 384 + kc * 16;
        #pragma unroll
        for (int np = 0; np < 4; np++) {
            uint32_t b0, b1, b2, b3;
            uint32_t addr = sbase + ((np * 16 + lrow) * BSTRIDE + k0 + lkof) * 2;
            ldm4(b0, b1, b2, b3, addr);
            mma16816(acc[2 * np],     a0, a1, a2, a3, b0, b1);
            mma16816(acc[2 * np + 1], a0, a1, a2, a3, b2, b3);
        }
    }

    // ---- LIF epilogue: thread owns rows {row0,row1} x cols {nt*8+2tg,+1} ----
    float* s_out = out + (size_t)BB * DD;
    float* u_out = s_out + (size_t)NN * BB * DD;
    float* i_out = u_out + (size_t)NN * BB * DD;

    #pragma unroll
    for (int nt = 0; nt < 8; nt++) {
        const int c = nt * 8 + 2 * tg;
        const float2 bb = __ldg((const float2*)(bias + n * DD + c));
        #pragma unroll
        for (int h = 0; h < 2; h++) {
            const int row = h ? row1 : row0;
            const size_t base = ((size_t)(n * BB) + row) * DD + c;
            float2 uu = *(const float2*)(u + base);
            float2 ii = *(const float2*)(i_syn + base);
            float ax = acc[nt][2 * h]     + bb.x;
            float ay = acc[nt][2 * h + 1] + bb.y;

            float inx = fmaf(0.9f, ii.x, ax);
            float iny = fmaf(0.9f, ii.y, ay);
            float unx = fmaf(0.95f, uu.x, 0.05f * inx);
            float uny = fmaf(0.95f, uu.y, 0.05f * iny);
            float svx = (unx - 1.0f > 0.0f) ? 1.0f : 0.0f;
            float svy = (uny - 1.0f > 0.0f) ? 1.0f : 0.0f;
            float2 sv = make_float2(svx, svy);
            float2 uo = make_float2(svx > 0.5f ? 0.0f : unx,
                                    svy > 0.5f ? 0.0f : uny);
            float2 iv = make_float2(inx, iny);

            *(float2*)(s_out + base) = sv;
            *(float2*)(u_out + base) = uo;
            *(float2*)(i_out + base) = iv;
            if (n == FINAL_ID)
                *(float2*)(out + (size_t)row * DD + c) = sv;
        }
    }
}

// ---------------------------------------------------------------------------
extern "C" void kernel_launch(void* const* d_in, const int* in_sizes, int n_in,
                              void* d_out, int out_size) {
    const float* inputs = (const float*)d_in[0];
    const float* u      = (const float*)d_in[1];
    const float* i_syn  = (const float*)d_in[2];
    const float* s_prev = (const float*)d_in[3];
    const float* W      = (const float*)d_in[4];
    const float* bias   = (const float*)d_in[5];
    const int*   conn   = (const int*)d_in[6];
    float* out = (float*)d_out;

    pack_kernel<<<(NN * BB) / 64, 256>>>(s_prev);
    prep_x_kernel<<<(BB * 32) / 256, 256>>>(inputs);
    prep_w_kernel<<<NN * 64, 256>>>(W);

    const int smem = 64 * BSTRIDE * 2;              // 91,136 B
    cudaFuncSetAttribute(snn_mma_kernel,
                         cudaFuncAttributeMaxDynamicSharedMemorySize, smem);
    dim3 grid(NN, BB / 128);
    snn_mma_kernel<<<grid, 256, smem>>>(u, i_syn, bias, conn, out);
}